// round 1
// baseline (speedup 1.0000x reference)
#include <cuda_runtime.h>
#include <cstdint>

#define BB   8
#define NN   8192
#define EE   262144
#define FIN  64
#define HH   128
#define FOUT 32
#define TOT  (BB*NN)   // 65536 rows total

// ---------------- device scratch (no allocations allowed) ----------------
__device__ float g_h0[(size_t)TOT*HH];
__device__ float g_hc[(size_t)TOT*HH];
__device__ float g_h1[(size_t)TOT*HH];
__device__ float g_h2[(size_t)TOT*HH];
__device__ int   g_cnt[TOT];
__device__ int   g_cursor[TOT];
__device__ int   g_rowstart[TOT];
__device__ float g_deg[TOT];
__device__ int   g_ccol[(size_t)BB*EE];
__device__ float g_cval[(size_t)BB*EE];
__device__ float g_stat[6*HH];         // [stage][sum|sumsq][H], stages 0..2
__device__ float g_M[HH*HH];           // W02 @ Wc
__device__ float g_Wa[HH*HH];
__device__ float g_ba[HH];
__device__ float g_Wb[HH*HH];
__device__ float g_bb[HH];
__device__ float g_Wo[HH*FOUT];
__device__ float g_bo[FOUT];
__device__ float g_s[HH];
__device__ float g_t[HH];

// ---------------- init: zero accumulators, seed fused biases ----------------
__global__ void init_kernel(const float* __restrict__ b02, const float* __restrict__ Wc,
                            const float* __restrict__ bc,  const float* __restrict__ b1,
                            const float* __restrict__ b2)
{
    int gid = blockIdx.x * 256 + threadIdx.x;
    if (gid < TOT) { g_cnt[gid] = 0; g_deg[gid] = 0.f; }
    if (gid < 6*HH) g_stat[gid] = 0.f;
    if (blockIdx.x == gridDim.x - 1) {
        int k = threadIdx.x;
        if (k < HH) {
            float s = bc[k];
            #pragma unroll 4
            for (int f = 0; f < HH; f++) s += b02[f] * Wc[f*HH + k];
            g_ba[k] = s;          // (b02 @ Wc + bc); fold_w adds t0 @ M
            g_bb[k] = b1[k];
        }
        if (k < FOUT) g_bo[k] = b2[k];
    }
}

// ---------------- M = W02 @ Wc (tiny) ----------------
__global__ void mm128_kernel(const float* __restrict__ W02, const float* __restrict__ Wc)
{
    __shared__ float row[HH];
    int f = blockIdx.x, k = threadIdx.x;
    row[k] = W02[f*HH + k];
    __syncthreads();
    float s = 0.f;
    #pragma unroll 4
    for (int j = 0; j < HH; j++) s = fmaf(row[j], Wc[j*HH + k], s);
    g_M[f*HH + k] = s;
}

// ---------------- BN stats -> per-feature affine (s, t) ----------------
__global__ void fold_st_kernel(const float* __restrict__ bnw, const float* __restrict__ bnb,
                               int stage)
{
    int f = threadIdx.x;
    float cnt = (float)TOT;
    float sum = g_stat[stage*2*HH + f];
    float sq  = g_stat[stage*2*HH + HH + f];
    float m = sum / cnt;
    float v = sq / cnt - m*m;
    float inv = rsqrtf(v + 1e-5f);
    float s = bnw[f] * inv;
    g_s[f] = s;
    g_t[f] = bnb[f] - m * s;
}

// Wdst[f,k] = s[f]*Msrc[f,k];  bias[k] += t[f]*Msrc[f,k]
template<int NC>
__global__ void fold_w_kernel(const float* __restrict__ Msrc, float* __restrict__ Wdst,
                              float* __restrict__ bias)
{
    int f = blockIdx.x, k = threadIdx.x;
    float s = g_s[f], t = g_t[f];
    float m = Msrc[f*NC + k];
    Wdst[f*NC + k] = s * m;
    atomicAdd(&bias[k], t * m);
}

// ---------------- CSR build ----------------
__global__ void count_kernel(const int* __restrict__ rows, const float* __restrict__ vals)
{
    int gid = blockIdx.x * 256 + threadIdx.x;
    if (gid >= BB*EE) return;
    int b = gid >> 18;                 // E = 2^18
    int r = rows[gid];
    atomicAdd(&g_cnt[b*NN + r], 1);
    atomicAdd(&g_deg[b*NN + r], vals[gid]);
}

__global__ void scan_kernel()          // grid=8 (batches), block=1024
{
    int b = blockIdx.x, t = threadIdx.x;
    int base = b*NN + t*8;
    int v[8], pre[8], tot = 0;
    #pragma unroll
    for (int i = 0; i < 8; i++) { v[i] = g_cnt[base+i]; pre[i] = tot; tot += v[i]; }
    int lane = t & 31, w = t >> 5;
    int x = tot;
    #pragma unroll
    for (int o = 1; o < 32; o <<= 1) { int y = __shfl_up_sync(0xffffffffu, x, o); if (lane >= o) x += y; }
    __shared__ int wsum[32];
    if (lane == 31) wsum[w] = x;
    __syncthreads();
    if (w == 0) {
        int y = wsum[lane];
        #pragma unroll
        for (int o = 1; o < 32; o <<= 1) { int z = __shfl_up_sync(0xffffffffu, y, o); if (lane >= o) y += z; }
        wsum[lane] = y;
    }
    __syncthreads();
    int ex = x - tot + (w > 0 ? wsum[w-1] : 0);
    #pragma unroll
    for (int i = 0; i < 8; i++) {
        int st = ex + pre[i];
        g_rowstart[base+i] = st;
        g_cursor[base+i]  = st;
    }
}

__global__ void scatter_kernel(const int* __restrict__ rows, const int* __restrict__ cols,
                               const float* __restrict__ vals)
{
    int gid = blockIdx.x * 256 + threadIdx.x;
    if (gid >= BB*EE) return;
    int b = gid >> 18;
    int r = rows[gid];
    int pos = atomicAdd(&g_cursor[b*NN + r], 1);
    g_ccol[(size_t)b*EE + pos] = cols[gid];
    g_cval[(size_t)b*EE + pos] = vals[gid];
}

// ---------------- SpMM aggregate + degree-norm + mask + relu + bnc stats ----------------
__global__ void agg_kernel(const int* __restrict__ num_nodes)   // grid=TOT/8, block=128
{
    int f = threadIdx.x;
    float ls = 0.f, lq = 0.f;
    #pragma unroll 1
    for (int i = 0; i < 8; i++) {
        int idx = blockIdx.x * 8 + i;
        int b = idx >> 13;             // N = 2^13
        int r = idx & (NN - 1);
        int start = g_rowstart[idx];
        int len   = g_cnt[idx];
        const float* hcb = g_hc + (size_t)b*NN*HH;
        size_t base = (size_t)b*EE + start;
        float acc = 0.f;
        int e = 0;
        for (; e + 4 <= len; e += 4) {
            int   c0 = g_ccol[base+e+0], c1 = g_ccol[base+e+1];
            int   c2 = g_ccol[base+e+2], c3 = g_ccol[base+e+3];
            float v0 = g_cval[base+e+0], v1 = g_cval[base+e+1];
            float v2 = g_cval[base+e+2], v3 = g_cval[base+e+3];
            acc = fmaf(v0, hcb[(size_t)c0*HH + f], acc);
            acc = fmaf(v1, hcb[(size_t)c1*HH + f], acc);
            acc = fmaf(v2, hcb[(size_t)c2*HH + f], acc);
            acc = fmaf(v3, hcb[(size_t)c3*HH + f], acc);
        }
        for (; e < len; e++) {
            int c = g_ccol[base+e];
            acc = fmaf(g_cval[base+e], hcb[(size_t)c*HH + f], acc);
        }
        float d = fmaxf(g_deg[idx], 1.f);
        float o = acc / d;
        if (r >= num_nodes[b]) o = 0.f;
        o = fmaxf(o, 0.f);
        g_h1[(size_t)idx*HH + f] = o;
        ls += o; lq += o*o;
    }
    atomicAdd(&g_stat[1*2*HH + f],      ls);
    atomicAdd(&g_stat[1*2*HH + HH + f], lq);
}

// ---------------- tiled fp32 GEMM: C[M,NC] = A[M,K] @ W[K,NC] + bias ----------------
// BM=128 rows/block, full K and NC in smem, 256 threads, 8x(NC/16) register micro-tile.
template<int K, int NC, bool RELU, int STAGE>   // STAGE<0: no stats
__global__ __launch_bounds__(256)
void gemm_kernel(const float* __restrict__ A, const float* __restrict__ Wm,
                 const float* __restrict__ bias, float* __restrict__ C)
{
    extern __shared__ float sm[];
    constexpr int AST = K + 1;                 // pad to break bank-cycle alignment
    float* As = sm;                            // [128][AST]
    float* Ws = sm + 128*AST;                  // [K][NC]
    int tid = threadIdx.x;
    size_t row0 = (size_t)blockIdx.x * 128;

    const float4* Ag = (const float4*)(A + row0*K);
    #pragma unroll 4
    for (int i = tid; i < 128*K/4; i += 256) {
        float4 v = Ag[i];
        int r = (i*4)/K, k = (i*4)%K;
        float* d = As + r*AST + k;
        d[0]=v.x; d[1]=v.y; d[2]=v.z; d[3]=v.w;
    }
    #pragma unroll 4
    for (int i = tid; i < K*NC/4; i += 256) ((float4*)Ws)[i] = ((const float4*)Wm)[i];
    __syncthreads();

    constexpr int CPT = NC/16;
    int cg = tid & 15, rg = tid >> 4;
    float acc[8][CPT];
    #pragma unroll
    for (int i = 0; i < 8; i++)
        #pragma unroll
        for (int j = 0; j < CPT; j++) acc[i][j] = 0.f;

    #pragma unroll 4
    for (int k = 0; k < K; k++) {
        float a[8], w[CPT];
        #pragma unroll
        for (int i = 0; i < 8; i++) a[i] = As[(rg*8 + i)*AST + k];
        #pragma unroll
        for (int j = 0; j < CPT; j++) w[j] = Ws[k*NC + cg*CPT + j];
        #pragma unroll
        for (int i = 0; i < 8; i++)
            #pragma unroll
            for (int j = 0; j < CPT; j++)
                acc[i][j] = fmaf(a[i], w[j], acc[i][j]);
    }

    float ls[CPT], lq[CPT];
    #pragma unroll
    for (int j = 0; j < CPT; j++) {
        float bv = bias[cg*CPT + j];
        ls[j] = 0.f; lq[j] = 0.f;
        #pragma unroll
        for (int i = 0; i < 8; i++) {
            float v = acc[i][j] + bv;
            if (RELU) v = fmaxf(v, 0.f);
            C[(row0 + rg*8 + i)*NC + cg*CPT + j] = v;
            if (STAGE >= 0) { ls[j] += v; lq[j] += v*v; }
        }
    }

    if (STAGE >= 0) {
        __syncthreads();
        float* ps = sm;               // reuse As region: 2*16*NC floats << As
        float* pq = sm + 16*NC;
        #pragma unroll
        for (int j = 0; j < CPT; j++) {
            ps[rg*NC + cg*CPT + j] = ls[j];
            pq[rg*NC + cg*CPT + j] = lq[j];
        }
        __syncthreads();
        if (tid < NC) {
            float s = 0.f, q = 0.f;
            #pragma unroll
            for (int g = 0; g < 16; g++) { s += ps[g*NC + tid]; q += pq[g*NC + tid]; }
            atomicAdd(&g_stat[STAGE*2*HH + tid],      s);
            atomicAdd(&g_stat[STAGE*2*HH + HH + tid], q);
        }
    }
}

// ---------------- host launcher ----------------
extern "C" void kernel_launch(void* const* d_in, const int* in_sizes, int n_in,
                              void* d_out, int out_size)
{
    const float* x    = (const float*)d_in[0];
    const int*   erow = (const int*)  d_in[1];
    const int*   ecol = (const int*)  d_in[2];
    const float* evl  = (const float*)d_in[3];
    const int*   nn   = (const int*)  d_in[4];
    const float* W0   = (const float*)d_in[5];
    const float* b0   = (const float*)d_in[6];
    const float* W02  = (const float*)d_in[7];
    const float* b02  = (const float*)d_in[8];
    const float* Wc   = (const float*)d_in[9];
    const float* bc   = (const float*)d_in[10];
    const float* W1   = (const float*)d_in[11];
    const float* b1   = (const float*)d_in[12];
    const float* W2   = (const float*)d_in[13];
    const float* b2   = (const float*)d_in[14];
    const float* bn0w = (const float*)d_in[15];
    const float* bn0b = (const float*)d_in[16];
    const float* bncw = (const float*)d_in[17];
    const float* bncb = (const float*)d_in[18];
    const float* bn1w = (const float*)d_in[19];
    const float* bn1b = (const float*)d_in[20];
    float* out = (float*)d_out;

    float *p_h0, *p_hc, *p_h1, *p_h2, *p_M, *p_Wa, *p_ba, *p_Wb, *p_bb, *p_Wo, *p_bo;
    cudaGetSymbolAddress((void**)&p_h0, g_h0);
    cudaGetSymbolAddress((void**)&p_hc, g_hc);
    cudaGetSymbolAddress((void**)&p_h1, g_h1);
    cudaGetSymbolAddress((void**)&p_h2, g_h2);
    cudaGetSymbolAddress((void**)&p_M,  g_M);
    cudaGetSymbolAddress((void**)&p_Wa, g_Wa);
    cudaGetSymbolAddress((void**)&p_ba, g_ba);
    cudaGetSymbolAddress((void**)&p_Wb, g_Wb);
    cudaGetSymbolAddress((void**)&p_bb, g_bb);
    cudaGetSymbolAddress((void**)&p_Wo, g_Wo);
    cudaGetSymbolAddress((void**)&p_bo, g_bo);

    const size_t sm1 = (128*(FIN+1) + FIN*HH) * sizeof(float);   // K=64,NC=128
    const size_t sm2 = (128*(HH+1)  + HH*HH)  * sizeof(float);   // K=128,NC=128
    const size_t sm3 = (128*(HH+1)  + HH*FOUT)* sizeof(float);   // K=128,NC=32
    cudaFuncSetAttribute(gemm_kernel<FIN,HH,true,0>,  cudaFuncAttributeMaxDynamicSharedMemorySize, (int)sm1);
    cudaFuncSetAttribute(gemm_kernel<HH,HH,false,-1>, cudaFuncAttributeMaxDynamicSharedMemorySize, (int)sm2);
    cudaFuncSetAttribute(gemm_kernel<HH,HH,true,2>,   cudaFuncAttributeMaxDynamicSharedMemorySize, (int)sm2);
    cudaFuncSetAttribute(gemm_kernel<HH,FOUT,false,-1>, cudaFuncAttributeMaxDynamicSharedMemorySize, (int)sm3);

    // init + CSR build
    init_kernel<<<TOT/256 + 1, 256>>>(b02, Wc, bc, b1, b2);
    count_kernel<<<(BB*EE)/256, 256>>>(erow, evl);
    scan_kernel<<<BB, 1024>>>();
    scatter_kernel<<<(BB*EE)/256, 256>>>(erow, ecol, evl);

    // layer 0: h0 = relu(x@W0 + b0), bn0 stats fused
    gemm_kernel<FIN,HH,true,0><<<TOT/128, 256, sm1>>>(x, W0, b0, p_h0);

    // fold bn0 into (W02@Wc)
    mm128_kernel<<<HH, HH>>>(W02, Wc);
    fold_st_kernel<<<1, HH>>>(bn0w, bn0b, 0);
    fold_w_kernel<HH><<<HH, HH>>>(p_M, p_Wa, p_ba);

    // hc = h0 @ Wa + ba
    gemm_kernel<HH,HH,false,-1><<<TOT/128, 256, sm2>>>(p_h0, p_Wa, p_ba, p_hc);

    // SGC aggregate (+mask, relu, bnc stats)
    agg_kernel<<<TOT/8, 128>>>(nn);

    // fold bnc into W1
    fold_st_kernel<<<1, HH>>>(bncw, bncb, 1);
    fold_w_kernel<HH><<<HH, HH>>>(W1, p_Wb, p_bb);

    // h2 = relu(h1 @ Wb + bb), bn1 stats fused
    gemm_kernel<HH,HH,true,2><<<TOT/128, 256, sm2>>>(p_h1, p_Wb, p_bb, p_h2);

    // fold bn1 into W2
    fold_st_kernel<<<1, HH>>>(bn1w, bn1b, 2);
    fold_w_kernel<FOUT><<<HH, FOUT>>>(W2, p_Wo, p_bo);

    // out = h2 @ Wo + bo
    gemm_kernel<HH,FOUT,false,-1><<<TOT/128, 256, sm3>>>(p_h2, p_Wo, p_bo, out);
}

// round 2
// speedup vs baseline: 1.1716x; 1.1716x over previous
#include <cuda_runtime.h>
#include <cstdint>

#define BB   8
#define NN   8192
#define EE   262144
#define FIN  64
#define HH   128
#define FOUT 32
#define TOT  (BB*NN)   // 65536 rows total

typedef unsigned long long ull;

// ---------------- device scratch (no allocations allowed) ----------------
__device__ float g_h0[(size_t)TOT*HH];
__device__ float g_hc[(size_t)TOT*HH];
__device__ float g_h1[(size_t)TOT*HH];
__device__ float g_h2[(size_t)TOT*HH];
__device__ int   g_cnt[TOT];
__device__ int   g_cursor[TOT];
__device__ int   g_rowstart[TOT];
__device__ int2  g_edge[(size_t)BB*EE];     // {col, val-as-int-bits}
__device__ float g_stat[6*HH];              // [stage][sum|sumsq][H], stages 0..2
__device__ float g_M[HH*HH];                // W02 @ Wc
__device__ float g_Wa[HH*HH];
__device__ float g_ba[HH];
__device__ float g_Wb[HH*HH];
__device__ float g_bb[HH];
__device__ float g_Wo[HH*FOUT];
__device__ float g_bo[FOUT];
__device__ float g_s[HH];
__device__ float g_t[HH];

__device__ __forceinline__ ull dup_f32(float a) {
    ull d; asm("mov.b64 %0, {%1, %1};" : "=l"(d) : "f"(a)); return d;
}
__device__ __forceinline__ void fma2(ull& acc, ull a, ull b) {
    asm("fma.rn.f32x2 %0, %1, %2, %0;" : "+l"(acc) : "l"(a), "l"(b));
}
__device__ __forceinline__ void unpack2(float& lo, float& hi, ull v) {
    asm("mov.b64 {%0, %1}, %2;" : "=f"(lo), "=f"(hi) : "l"(v));
}

// ---------------- init: zero accumulators, seed fused biases ----------------
__global__ void init_kernel(const float* __restrict__ b02, const float* __restrict__ Wc,
                            const float* __restrict__ bc,  const float* __restrict__ b1,
                            const float* __restrict__ b2)
{
    int gid = blockIdx.x * 256 + threadIdx.x;
    if (gid < TOT) g_cnt[gid] = 0;
    if (gid < 6*HH) g_stat[gid] = 0.f;
    if (blockIdx.x == gridDim.x - 1) {
        int k = threadIdx.x;
        if (k < HH) {
            float s = bc[k];
            #pragma unroll 4
            for (int f = 0; f < HH; f++) s += b02[f] * Wc[f*HH + k];
            g_ba[k] = s;          // (b02 @ Wc + bc); fold_w adds t0 @ M
            g_bb[k] = b1[k];
        }
        if (k < FOUT) g_bo[k] = b2[k];
    }
}

// ---------------- M = W02 @ Wc (tiny) ----------------
__global__ void mm128_kernel(const float* __restrict__ W02, const float* __restrict__ Wc)
{
    __shared__ float row[HH];
    int f = blockIdx.x, k = threadIdx.x;
    row[k] = W02[f*HH + k];
    __syncthreads();
    float s = 0.f;
    #pragma unroll 4
    for (int j = 0; j < HH; j++) s = fmaf(row[j], Wc[j*HH + k], s);
    g_M[f*HH + k] = s;
}

// ---------------- BN stats -> per-feature affine (s, t) ----------------
__global__ void fold_st_kernel(const float* __restrict__ bnw, const float* __restrict__ bnb,
                               int stage)
{
    int f = threadIdx.x;
    float cnt = (float)TOT;
    float sum = g_stat[stage*2*HH + f];
    float sq  = g_stat[stage*2*HH + HH + f];
    float m = sum / cnt;
    float v = sq / cnt - m*m;
    float inv = rsqrtf(v + 1e-5f);
    float s = bnw[f] * inv;
    g_s[f] = s;
    g_t[f] = bnb[f] - m * s;
}

// Wdst[f,k] = s[f]*Msrc[f,k];  bias[k] += t[f]*Msrc[f,k]
template<int NC>
__global__ void fold_w_kernel(const float* __restrict__ Msrc, float* __restrict__ Wdst,
                              float* __restrict__ bias)
{
    int f = blockIdx.x, k = threadIdx.x;
    float s = g_s[f], t = g_t[f];
    float m = Msrc[f*NC + k];
    Wdst[f*NC + k] = s * m;
    atomicAdd(&bias[k], t * m);
}

// ---------------- CSR build ----------------
__global__ void count_kernel(const int* __restrict__ rows)
{
    int gid = blockIdx.x * 256 + threadIdx.x;
    if (gid >= BB*EE) return;
    int b = gid >> 18;                 // E = 2^18
    int r = rows[gid];
    atomicAdd(&g_cnt[b*NN + r], 1);
}

__global__ void scan_kernel()          // grid=8 (batches), block=1024
{
    int b = blockIdx.x, t = threadIdx.x;
    int base = b*NN + t*8;
    int v[8], pre[8], tot = 0;
    #pragma unroll
    for (int i = 0; i < 8; i++) { v[i] = g_cnt[base+i]; pre[i] = tot; tot += v[i]; }
    int lane = t & 31, w = t >> 5;
    int x = tot;
    #pragma unroll
    for (int o = 1; o < 32; o <<= 1) { int y = __shfl_up_sync(0xffffffffu, x, o); if (lane >= o) x += y; }
    __shared__ int wsum[32];
    if (lane == 31) wsum[w] = x;
    __syncthreads();
    if (w == 0) {
        int y = wsum[lane];
        #pragma unroll
        for (int o = 1; o < 32; o <<= 1) { int z = __shfl_up_sync(0xffffffffu, y, o); if (lane >= o) y += z; }
        wsum[lane] = y;
    }
    __syncthreads();
    int ex = x - tot + (w > 0 ? wsum[w-1] : 0);
    #pragma unroll
    for (int i = 0; i < 8; i++) {
        int st = ex + pre[i];
        g_rowstart[base+i] = st;
        g_cursor[base+i]  = st;
    }
}

__global__ void scatter_kernel(const int* __restrict__ rows, const int* __restrict__ cols,
                               const float* __restrict__ vals)
{
    int gid = blockIdx.x * 256 + threadIdx.x;
    if (gid >= BB*EE) return;
    int b = gid >> 18;
    int r = rows[gid];
    int pos = atomicAdd(&g_cursor[b*NN + r], 1);
    g_edge[(size_t)b*EE + pos] = make_int2(cols[gid], __float_as_int(vals[gid]));
}

// ---------------- SpMM aggregate + degree-norm + mask + relu + bnc stats ----------------
__global__ void agg_kernel(const int* __restrict__ num_nodes)   // grid=TOT/8, block=128
{
    int f = threadIdx.x;
    float ls = 0.f, lq = 0.f;
    #pragma unroll 1
    for (int i = 0; i < 8; i++) {
        int idx = blockIdx.x * 8 + i;
        int b = idx >> 13;             // N = 2^13
        int r = idx & (NN - 1);
        int start = g_rowstart[idx];
        int len   = g_cnt[idx];
        const float* hcb = g_hc + (size_t)b*NN*HH;
        const int2* ep = g_edge + (size_t)b*EE + start;
        float acc = 0.f, dsum = 0.f;
        int e = 0;
        for (; e + 4 <= len; e += 4) {
            int2 e0 = ep[e+0], e1 = ep[e+1], e2 = ep[e+2], e3 = ep[e+3];
            float v0 = __int_as_float(e0.y), v1 = __int_as_float(e1.y);
            float v2 = __int_as_float(e2.y), v3 = __int_as_float(e3.y);
            acc = fmaf(v0, hcb[(size_t)e0.x*HH + f], acc);
            acc = fmaf(v1, hcb[(size_t)e1.x*HH + f], acc);
            acc = fmaf(v2, hcb[(size_t)e2.x*HH + f], acc);
            acc = fmaf(v3, hcb[(size_t)e3.x*HH + f], acc);
            dsum += (v0 + v1) + (v2 + v3);
        }
        for (; e < len; e++) {
            int2 e0 = ep[e];
            float v = __int_as_float(e0.y);
            acc = fmaf(v, hcb[(size_t)e0.x*HH + f], acc);
            dsum += v;
        }
        float d = fmaxf(dsum, 1.f);
        float o = acc / d;
        if (r >= num_nodes[b]) o = 0.f;
        o = fmaxf(o, 0.f);
        g_h1[(size_t)idx*HH + f] = o;
        ls += o; lq += o*o;
    }
    atomicAdd(&g_stat[1*2*HH + f],      ls);
    atomicAdd(&g_stat[1*2*HH + HH + f], lq);
}

// ---------------- tiled fp32 GEMM with packed f32x2 FMAs ----------------
// C[M,NC] = A[M,K] @ W[K,NC] + bias.  BM=128 rows/block, 256 threads,
// micro-tile 8 rows x CPT cols per thread, columns processed in f32x2 pairs.
template<int K, int NC, bool RELU, int STAGE>   // STAGE<0: no stats
__global__ __launch_bounds__(256)
void gemm_kernel(const float* __restrict__ A, const float* __restrict__ Wm,
                 const float* __restrict__ bias, float* __restrict__ C)
{
    extern __shared__ float sm[];
    constexpr int AST = K + 4;                 // pad (mult of 4 keeps 16B align)
    float* As = sm;                            // [128][AST]
    float* Ws = sm + 128*AST;                  // [K][NC]
    int tid = threadIdx.x;
    size_t row0 = (size_t)blockIdx.x * 128;

    const float4* Ag = (const float4*)(A + row0*K);
    #pragma unroll 4
    for (int i = tid; i < 128*K/4; i += 256) {
        float4 v = Ag[i];
        int r = (i*4)/K, k = (i*4)%K;
        *(float4*)&As[r*AST + k] = v;
    }
    #pragma unroll 4
    for (int i = tid; i < K*NC/4; i += 256) ((float4*)Ws)[i] = ((const float4*)Wm)[i];
    __syncthreads();

    constexpr int CPT = NC/16;    // 8 (NC=128) or 2 (NC=32)
    constexpr int CP2 = CPT/2;    // packed column pairs
    int cg = tid & 15, rg = tid >> 4;
    const float* Arow = As + rg*8*AST;
    const float* Wcol = Ws + cg*CPT;

    ull acc[8][CP2];
    #pragma unroll
    for (int i = 0; i < 8; i++)
        #pragma unroll
        for (int j = 0; j < CP2; j++) acc[i][j] = 0ull;

    #pragma unroll 2
    for (int k0 = 0; k0 < K; k0 += 4) {
        float4 a4[8];
        #pragma unroll
        for (int i = 0; i < 8; i++) a4[i] = *(const float4*)&Arow[i*AST + k0];
        #pragma unroll
        for (int kk = 0; kk < 4; kk++) {
            ull w2[CP2];
            #pragma unroll
            for (int j = 0; j < CP2; j++)
                w2[j] = *(const ull*)&Wcol[(k0+kk)*NC + 2*j];
            #pragma unroll
            for (int i = 0; i < 8; i++) {
                float av = (kk == 0) ? a4[i].x : (kk == 1) ? a4[i].y
                         : (kk == 2) ? a4[i].z : a4[i].w;
                ull a2 = dup_f32(av);
                #pragma unroll
                for (int j = 0; j < CP2; j++) fma2(acc[i][j], a2, w2[j]);
            }
        }
    }

    float ls[CPT], lq[CPT];
    #pragma unroll
    for (int j = 0; j < CP2; j++) {
        int c0 = cg*CPT + 2*j;
        float b0v = bias[c0], b1v = bias[c0+1];
        ls[2*j] = 0.f; lq[2*j] = 0.f; ls[2*j+1] = 0.f; lq[2*j+1] = 0.f;
        #pragma unroll
        for (int i = 0; i < 8; i++) {
            float lo, hi;
            unpack2(lo, hi, acc[i][j]);
            float v0 = lo + b0v, v1 = hi + b1v;
            if (RELU) { v0 = fmaxf(v0, 0.f); v1 = fmaxf(v1, 0.f); }
            *(float2*)&C[(row0 + rg*8 + i)*NC + c0] = make_float2(v0, v1);
            if (STAGE >= 0) { ls[2*j] += v0; lq[2*j] += v0*v0; ls[2*j+1] += v1; lq[2*j+1] += v1*v1; }
        }
    }

    if (STAGE >= 0) {
        __syncthreads();
        float* ps = sm;               // reuse As region
        float* pq = sm + 16*NC;
        #pragma unroll
        for (int j = 0; j < CPT; j++) {
            ps[rg*NC + cg*CPT + j] = ls[j];
            pq[rg*NC + cg*CPT + j] = lq[j];
        }
        __syncthreads();
        if (tid < NC) {
            float s = 0.f, q = 0.f;
            #pragma unroll
            for (int g = 0; g < 16; g++) { s += ps[g*NC + tid]; q += pq[g*NC + tid]; }
            atomicAdd(&g_stat[STAGE*2*HH + tid],      s);
            atomicAdd(&g_stat[STAGE*2*HH + HH + tid], q);
        }
    }
}

// ---------------- host launcher ----------------
extern "C" void kernel_launch(void* const* d_in, const int* in_sizes, int n_in,
                              void* d_out, int out_size)
{
    const float* x    = (const float*)d_in[0];
    const int*   erow = (const int*)  d_in[1];
    const int*   ecol = (const int*)  d_in[2];
    const float* evl  = (const float*)d_in[3];
    const int*   nn   = (const int*)  d_in[4];
    const float* W0   = (const float*)d_in[5];
    const float* b0   = (const float*)d_in[6];
    const float* W02  = (const float*)d_in[7];
    const float* b02  = (const float*)d_in[8];
    const float* Wc   = (const float*)d_in[9];
    const float* bc   = (const float*)d_in[10];
    const float* W1   = (const float*)d_in[11];
    const float* b1   = (const float*)d_in[12];
    const float* W2   = (const float*)d_in[13];
    const float* b2   = (const float*)d_in[14];
    const float* bn0w = (const float*)d_in[15];
    const float* bn0b = (const float*)d_in[16];
    const float* bncw = (const float*)d_in[17];
    const float* bncb = (const float*)d_in[18];
    const float* bn1w = (const float*)d_in[19];
    const float* bn1b = (const float*)d_in[20];
    float* out = (float*)d_out;

    float *p_h0, *p_hc, *p_h1, *p_h2, *p_M, *p_Wa, *p_ba, *p_Wb, *p_bb, *p_Wo, *p_bo;
    cudaGetSymbolAddress((void**)&p_h0, g_h0);
    cudaGetSymbolAddress((void**)&p_hc, g_hc);
    cudaGetSymbolAddress((void**)&p_h1, g_h1);
    cudaGetSymbolAddress((void**)&p_h2, g_h2);
    cudaGetSymbolAddress((void**)&p_M,  g_M);
    cudaGetSymbolAddress((void**)&p_Wa, g_Wa);
    cudaGetSymbolAddress((void**)&p_ba, g_ba);
    cudaGetSymbolAddress((void**)&p_Wb, g_Wb);
    cudaGetSymbolAddress((void**)&p_bb, g_bb);
    cudaGetSymbolAddress((void**)&p_Wo, g_Wo);
    cudaGetSymbolAddress((void**)&p_bo, g_bo);

    const size_t sm1 = (128*(FIN+4) + (size_t)FIN*HH) * sizeof(float);   // K=64,NC=128
    const size_t sm2 = (128*(HH+4)  + (size_t)HH*HH)  * sizeof(float);   // K=128,NC=128
    const size_t sm3 = (128*(HH+4)  + (size_t)HH*FOUT)* sizeof(float);   // K=128,NC=32
    cudaFuncSetAttribute(gemm_kernel<FIN,HH,true,0>,    cudaFuncAttributeMaxDynamicSharedMemorySize, (int)sm1);
    cudaFuncSetAttribute(gemm_kernel<HH,HH,false,-1>,   cudaFuncAttributeMaxDynamicSharedMemorySize, (int)sm2);
    cudaFuncSetAttribute(gemm_kernel<HH,HH,true,2>,     cudaFuncAttributeMaxDynamicSharedMemorySize, (int)sm2);
    cudaFuncSetAttribute(gemm_kernel<HH,FOUT,false,-1>, cudaFuncAttributeMaxDynamicSharedMemorySize, (int)sm3);

    // init + CSR build
    init_kernel<<<TOT/256 + 1, 256>>>(b02, Wc, bc, b1, b2);
    count_kernel<<<(BB*EE)/256, 256>>>(erow);
    scan_kernel<<<BB, 1024>>>();
    scatter_kernel<<<(BB*EE)/256, 256>>>(erow, ecol, evl);

    // layer 0: h0 = relu(x@W0 + b0), bn0 stats fused
    gemm_kernel<FIN,HH,true,0><<<TOT/128, 256, sm1>>>(x, W0, b0, p_h0);

    // fold bn0 into (W02@Wc)
    mm128_kernel<<<HH, HH>>>(W02, Wc);
    fold_st_kernel<<<1, HH>>>(bn0w, bn0b, 0);
    fold_w_kernel<HH><<<HH, HH>>>(p_M, p_Wa, p_ba);

    // hc = h0 @ Wa + ba
    gemm_kernel<HH,HH,false,-1><<<TOT/128, 256, sm2>>>(p_h0, p_Wa, p_ba, p_hc);

    // SGC aggregate (+mask, relu, bnc stats)
    agg_kernel<<<TOT/8, 128>>>(nn);

    // fold bnc into W1
    fold_st_kernel<<<1, HH>>>(bncw, bncb, 1);
    fold_w_kernel<HH><<<HH, HH>>>(W1, p_Wb, p_bb);

    // h2 = relu(h1 @ Wb + bb), bn1 stats fused
    gemm_kernel<HH,HH,true,2><<<TOT/128, 256, sm2>>>(p_h1, p_Wb, p_bb, p_h2);

    // fold bn1 into W2
    fold_st_kernel<<<1, HH>>>(bn1w, bn1b, 2);
    fold_w_kernel<FOUT><<<HH, FOUT>>>(W2, p_Wo, p_bo);

    // out = h2 @ Wo + bo
    gemm_kernel<HH,FOUT,false,-1><<<TOT/128, 256, sm3>>>(p_h2, p_Wo, p_bo, out);
}

// round 5
// speedup vs baseline: 1.2538x; 1.0702x over previous
#include <cuda_runtime.h>
#include <cuda_fp16.h>
#include <cstdint>

#define BB   8
#define NN   8192
#define EE   262144
#define FIN  64
#define HH   128
#define FOUT 32
#define TOT  (BB*NN)   // 65536 rows total

typedef unsigned long long ull;
typedef unsigned int uint;

// ---------------- device scratch (no allocations allowed) ----------------
__device__ float g_h0[(size_t)TOT*HH];
__device__ uint  g_hcp[(size_t)TOT*(HH/2)];   // hc as fp16x2 pairs
__device__ float g_h1[(size_t)TOT*HH];
__device__ float g_h2[(size_t)TOT*HH];
__device__ int   g_cnt[TOT];
__device__ int   g_cursor[TOT];
__device__ int   g_rowstart[TOT];
__device__ uint  g_epk[(size_t)BB*EE];        // packed edge: [fp16 val | 16-bit col]
__device__ float g_stat[6*HH];                // [stage][sum|sumsq][H], stages 0..2
__device__ float g_M[HH*HH];                  // W02 @ Wc
__device__ float g_Wa[HH*HH];
__device__ float g_ba[HH];
__device__ float g_Wb[HH*HH];
__device__ float g_bb[HH];
__device__ float g_Wo[HH*FOUT];
__device__ float g_bo[FOUT];

__device__ __forceinline__ ull dup_f32(float a) {
    ull d; asm("mov.b64 %0, {%1, %1};" : "=l"(d) : "f"(a)); return d;
}
__device__ __forceinline__ void fma2(ull& acc, ull a, ull b) {
    asm("fma.rn.f32x2 %0, %1, %2, %0;" : "+l"(acc) : "l"(a), "l"(b));
}
__device__ __forceinline__ void unpack2(float& lo, float& hi, ull v) {
    asm("mov.b64 {%0, %1}, %2;" : "=f"(lo), "=f"(hi) : "l"(v));
}
__device__ __forceinline__ float2 h2f(uint p) {
    return __half22float2(*reinterpret_cast<__half2*>(&p));
}

// ---------------- init: zero accumulators, seed fused bias for Wa ----------------
__global__ void init_kernel(const float* __restrict__ b02, const float* __restrict__ Wc,
                            const float* __restrict__ bc)
{
    int gid = blockIdx.x * 256 + threadIdx.x;
    if (gid < TOT) g_cnt[gid] = 0;
    if (gid < 6*HH) g_stat[gid] = 0.f;
    if (blockIdx.x == gridDim.x - 1 && threadIdx.x < HH) {
        int k = threadIdx.x;
        float s = bc[k];
        #pragma unroll 4
        for (int f = 0; f < HH; f++) s += b02[f] * Wc[f*HH + k];
        g_ba[k] = s;          // (b02 @ Wc + bc); fold adds t0 @ M
    }
}

// ---------------- M = W02 @ Wc (tiny) ----------------
__global__ void mm128_kernel(const float* __restrict__ W02, const float* __restrict__ Wc)
{
    __shared__ float row[HH];
    int f = blockIdx.x, k = threadIdx.x;
    row[k] = W02[f*HH + k];
    __syncthreads();
    float s = 0.f;
    #pragma unroll 4
    for (int j = 0; j < HH; j++) s = fmaf(row[j], Wc[j*HH + k], s);
    g_M[f*HH + k] = s;
}

// ---------------- BN fold: stats -> affine, applied to weight + bias ----------------
// Wdst[f,k] = s[f]*Msrc[f,k];  bias_out[k] = bias_in[k] + sum_f t[f]*Msrc[f,k]
__global__ void fold_kernel(const float* __restrict__ bnw, const float* __restrict__ bnb,
                            int stage, const float* __restrict__ Msrc,
                            float* __restrict__ Wdst,
                            const float* __restrict__ bias_in, float* __restrict__ bias_out,
                            int NC)
{
    __shared__ float ss[HH], st[HH];
    int tid = threadIdx.x;    // 128
    {
        float cnt = (float)TOT;
        float sum = g_stat[stage*2*HH + tid];
        float sq  = g_stat[stage*2*HH + HH + tid];
        float m = sum / cnt;
        float v = sq / cnt - m*m;
        float inv = rsqrtf(v + 1e-5f);
        float s = bnw[tid] * inv;
        ss[tid] = s;
        st[tid] = bnb[tid] - m * s;
    }
    __syncthreads();
    if (tid < NC) {
        float acc = bias_in[tid];
        #pragma unroll 4
        for (int f = 0; f < HH; f++) {
            float m = Msrc[f*NC + tid];
            Wdst[f*NC + tid] = ss[f] * m;
            acc = fmaf(st[f], m, acc);
        }
        bias_out[tid] = acc;
    }
}

// ---------------- CSR build ----------------
__global__ void count_kernel(const int* __restrict__ rows)
{
    int gid = blockIdx.x * 256 + threadIdx.x;
    if (gid >= BB*EE) return;
    int b = gid >> 18;                 // E = 2^18
    int r = rows[gid];
    atomicAdd(&g_cnt[b*NN + r], 1);
}

__global__ void scan_kernel()          // grid=8 (batches), block=1024
{
    int b = blockIdx.x, t = threadIdx.x;
    int base = b*NN + t*8;
    int v[8], pre[8], tot = 0;
    #pragma unroll
    for (int i = 0; i < 8; i++) { v[i] = g_cnt[base+i]; pre[i] = tot; tot += v[i]; }
    int lane = t & 31, w = t >> 5;
    int x = tot;
    #pragma unroll
    for (int o = 1; o < 32; o <<= 1) { int y = __shfl_up_sync(0xffffffffu, x, o); if (lane >= o) x += y; }
    __shared__ int wsum[32];
    if (lane == 31) wsum[w] = x;
    __syncthreads();
    if (w == 0) {
        int y = wsum[lane];
        #pragma unroll
        for (int o = 1; o < 32; o <<= 1) { int z = __shfl_up_sync(0xffffffffu, y, o); if (lane >= o) y += z; }
        wsum[lane] = y;
    }
    __syncthreads();
    int ex = x - tot + (w > 0 ? wsum[w-1] : 0);
    #pragma unroll
    for (int i = 0; i < 8; i++) {
        int st = ex + pre[i];
        g_rowstart[base+i] = st;
        g_cursor[base+i]  = st;
    }
}

__global__ void scatter_kernel(const int* __restrict__ rows, const int* __restrict__ cols,
                               const float* __restrict__ vals)
{
    int gid = blockIdx.x * 256 + threadIdx.x;
    if (gid >= BB*EE) return;
    int b = gid >> 18;
    int r = rows[gid];
    int pos = atomicAdd(&g_cursor[b*NN + r], 1);
    uint vh = (uint)__half_as_ushort(__float2half_rn(vals[gid]));
    g_epk[(size_t)b*EE + pos] = (vh << 16) | (uint)cols[gid];
}

// ---------------- SpMM aggregate (fp16 gather) + norm + mask + relu + bnc stats --------
// grid = TOT/8, block = 128 (4 warps). Warp w handles rows {blk*8+w, blk*8+4+w}.
// Lane j owns features [4j, 4j+3]; per edge a warp gathers one hc row as 32x uint2.
__global__ void agg_kernel(const int* __restrict__ nn)
{
    __shared__ float s_ls[HH], s_lq[HH];
    int tid = threadIdx.x, w = tid >> 5, lane = tid & 31;
    for (int i = tid; i < HH; i += 128) { s_ls[i] = 0.f; s_lq[i] = 0.f; }
    __syncthreads();

    float ls[4] = {0,0,0,0}, lq[4] = {0,0,0,0};
    #pragma unroll 1
    for (int ri = 0; ri < 2; ri++) {
        int idx = blockIdx.x * 8 + ri*4 + w;
        int b = idx >> 13, r = idx & (NN - 1);
        int start = g_rowstart[idx], len = g_cnt[idx];
        const uint2* hcb = (const uint2*)g_hcp + (size_t)b*NN*32;
        const uint*  ep  = g_epk + (size_t)b*EE + start;

        float a0=0.f, a1=0.f, a2=0.f, a3=0.f, ds=0.f;
        for (int e0 = 0; e0 < len; e0 += 32) {
            uint my = (e0 + lane < len) ? ep[e0 + lane] : 0u;
            int m = min(32, len - e0);
            int t = 0;
            for (; t + 2 <= m; t += 2) {
                uint ea = __shfl_sync(0xffffffffu, my, t);
                uint eb = __shfl_sync(0xffffffffu, my, t+1);
                float va = __half2float(__ushort_as_half((unsigned short)(ea >> 16)));
                float vb = __half2float(__ushort_as_half((unsigned short)(eb >> 16)));
                uint2 ha = hcb[(size_t)(ea & 0xFFFFu)*32 + lane];
                uint2 hb = hcb[(size_t)(eb & 0xFFFFu)*32 + lane];
                float2 fa0 = h2f(ha.x), fa1 = h2f(ha.y);
                float2 fb0 = h2f(hb.x), fb1 = h2f(hb.y);
                a0 = fmaf(va, fa0.x, a0);  a1 = fmaf(va, fa0.y, a1);
                a2 = fmaf(va, fa1.x, a2);  a3 = fmaf(va, fa1.y, a3);
                a0 = fmaf(vb, fb0.x, a0);  a1 = fmaf(vb, fb0.y, a1);
                a2 = fmaf(vb, fb1.x, a2);  a3 = fmaf(vb, fb1.y, a3);
                ds += va + vb;
            }
            if (t < m) {
                uint ea = __shfl_sync(0xffffffffu, my, t);
                float va = __half2float(__ushort_as_half((unsigned short)(ea >> 16)));
                uint2 ha = hcb[(size_t)(ea & 0xFFFFu)*32 + lane];
                float2 fa0 = h2f(ha.x), fa1 = h2f(ha.y);
                a0 = fmaf(va, fa0.x, a0);  a1 = fmaf(va, fa0.y, a1);
                a2 = fmaf(va, fa1.x, a2);  a3 = fmaf(va, fa1.y, a3);
                ds += va;
            }
        }
        float inv = 1.f / fmaxf(ds, 1.f);
        bool dead = (r >= nn[b]);
        float4 o;
        o.x = dead ? 0.f : fmaxf(a0*inv, 0.f);
        o.y = dead ? 0.f : fmaxf(a1*inv, 0.f);
        o.z = dead ? 0.f : fmaxf(a2*inv, 0.f);
        o.w = dead ? 0.f : fmaxf(a3*inv, 0.f);
        *(float4*)&g_h1[(size_t)idx*HH + lane*4] = o;
        ls[0]+=o.x; lq[0]+=o.x*o.x;  ls[1]+=o.y; lq[1]+=o.y*o.y;
        ls[2]+=o.z; lq[2]+=o.z*o.z;  ls[3]+=o.w; lq[3]+=o.w*o.w;
    }
    #pragma unroll
    for (int q = 0; q < 4; q++) {
        atomicAdd(&s_ls[lane*4+q], ls[q]);
        atomicAdd(&s_lq[lane*4+q], lq[q]);
    }
    __syncthreads();
    for (int i = tid; i < HH; i += 128) {
        atomicAdd(&g_stat[1*2*HH + i],      s_ls[i]);
        atomicAdd(&g_stat[1*2*HH + HH + i], s_lq[i]);
    }
}

// ---------------- tiled fp32 GEMM with packed f32x2 FMAs ----------------
template<int K, int NC, bool RELU, int STAGE, bool OUT16>   // STAGE<0: no stats
__global__ __launch_bounds__(256)
void gemm_kernel(const float* __restrict__ A, const float* __restrict__ Wm,
                 const float* __restrict__ bias, void* __restrict__ Cv)
{
    extern __shared__ float sm[];
    constexpr int AST = K + 4;
    float* As = sm;                            // [128][AST]
    float* Ws = sm + 128*AST;                  // [K][NC]
    int tid = threadIdx.x;
    size_t row0 = (size_t)blockIdx.x * 128;

    const float4* Ag = (const float4*)(A + row0*K);
    #pragma unroll 4
    for (int i = tid; i < 128*K/4; i += 256) {
        float4 v = Ag[i];
        int r = (i*4)/K, k = (i*4)%K;
        *(float4*)&As[r*AST + k] = v;
    }
    #pragma unroll 4
    for (int i = tid; i < K*NC/4; i += 256) ((float4*)Ws)[i] = ((const float4*)Wm)[i];
    __syncthreads();

    constexpr int CPT = NC/16;    // 8 (NC=128) or 2 (NC=32)
    constexpr int CP2 = CPT/2;
    int cg = tid & 15, rg = tid >> 4;
    const float* Arow = As + rg*8*AST;
    const float* Wcol = Ws + cg*CPT;

    ull acc[8][CP2];
    #pragma unroll
    for (int i = 0; i < 8; i++)
        #pragma unroll
        for (int j = 0; j < CP2; j++) acc[i][j] = 0ull;

    #pragma unroll 2
    for (int k0 = 0; k0 < K; k0 += 4) {
        float4 a4[8];
        #pragma unroll
        for (int i = 0; i < 8; i++) a4[i] = *(const float4*)&Arow[i*AST + k0];
        #pragma unroll
        for (int kk = 0; kk < 4; kk++) {
            ull w2[CP2];
            #pragma unroll
            for (int j = 0; j < CP2; j++)
                w2[j] = *(const ull*)&Wcol[(k0+kk)*NC + 2*j];
            #pragma unroll
            for (int i = 0; i < 8; i++) {
                float av = (kk == 0) ? a4[i].x : (kk == 1) ? a4[i].y
                         : (kk == 2) ? a4[i].z : a4[i].w;
                ull a2 = dup_f32(av);
                #pragma unroll
                for (int j = 0; j < CP2; j++) fma2(acc[i][j], a2, w2[j]);
            }
        }
    }

    float ls[CPT], lq[CPT];
    #pragma unroll
    for (int j = 0; j < CP2; j++) {
        int c0 = cg*CPT + 2*j;
        float b0v = bias[c0], b1v = bias[c0+1];
        ls[2*j] = 0.f; lq[2*j] = 0.f; ls[2*j+1] = 0.f; lq[2*j+1] = 0.f;
        #pragma unroll
        for (int i = 0; i < 8; i++) {
            float lo, hi;
            unpack2(lo, hi, acc[i][j]);
            float v0 = lo + b0v, v1 = hi + b1v;
            if (RELU) { v0 = fmaxf(v0, 0.f); v1 = fmaxf(v1, 0.f); }
            if (OUT16) {
                __half2 p = __float22half2_rn(make_float2(v0, v1));
                ((uint*)Cv)[(row0 + rg*8 + i)*(NC/2) + c0/2] = *(uint*)&p;
            } else {
                *(float2*)&((float*)Cv)[(row0 + rg*8 + i)*NC + c0] = make_float2(v0, v1);
            }
            if (STAGE >= 0) { ls[2*j] += v0; lq[2*j] += v0*v0; ls[2*j+1] += v1; lq[2*j+1] += v1*v1; }
        }
    }

    if (STAGE >= 0) {
        __syncthreads();
        float* ps = sm;
        float* pq = sm + 16*NC;
        #pragma unroll
        for (int j = 0; j < CPT; j++) {
            ps[rg*NC + cg*CPT + j] = ls[j];
            pq[rg*NC + cg*CPT + j] = lq[j];
        }
        __syncthreads();
        if (tid < NC) {
            float s = 0.f, q = 0.f;
            #pragma unroll
            for (int g = 0; g < 16; g++) { s += ps[g*NC + tid]; q += pq[g*NC + tid]; }
            atomicAdd(&g_stat[STAGE*2*HH + tid],      s);
            atomicAdd(&g_stat[STAGE*2*HH + HH + tid], q);
        }
    }
}

// ---------------- host launcher ----------------
extern "C" void kernel_launch(void* const* d_in, const int* in_sizes, int n_in,
                              void* d_out, int out_size)
{
    const float* x    = (const float*)d_in[0];
    const int*   erow = (const int*)  d_in[1];
    const int*   ecol = (const int*)  d_in[2];
    const float* evl  = (const float*)d_in[3];
    const int*   nn   = (const int*)  d_in[4];
    const float* W0   = (const float*)d_in[5];
    const float* b0   = (const float*)d_in[6];
    const float* W02  = (const float*)d_in[7];
    const float* b02  = (const float*)d_in[8];
    const float* Wc   = (const float*)d_in[9];
    const float* bc   = (const float*)d_in[10];
    const float* W1   = (const float*)d_in[11];
    const float* b1   = (const float*)d_in[12];
    const float* W2   = (const float*)d_in[13];
    const float* b2   = (const float*)d_in[14];
    const float* bn0w = (const float*)d_in[15];
    const float* bn0b = (const float*)d_in[16];
    const float* bncw = (const float*)d_in[17];
    const float* bncb = (const float*)d_in[18];
    const float* bn1w = (const float*)d_in[19];
    const float* bn1b = (const float*)d_in[20];
    float* out = (float*)d_out;

    float *p_h0, *p_h1, *p_h2, *p_M, *p_Wa, *p_ba, *p_Wb, *p_bb, *p_Wo, *p_bo;
    uint  *p_hcp;
    cudaGetSymbolAddress((void**)&p_h0,  g_h0);
    cudaGetSymbolAddress((void**)&p_hcp, g_hcp);
    cudaGetSymbolAddress((void**)&p_h1,  g_h1);
    cudaGetSymbolAddress((void**)&p_h2,  g_h2);
    cudaGetSymbolAddress((void**)&p_M,   g_M);
    cudaGetSymbolAddress((void**)&p_Wa,  g_Wa);
    cudaGetSymbolAddress((void**)&p_ba,  g_ba);
    cudaGetSymbolAddress((void**)&p_Wb,  g_Wb);
    cudaGetSymbolAddress((void**)&p_bb,  g_bb);
    cudaGetSymbolAddress((void**)&p_Wo,  g_Wo);
    cudaGetSymbolAddress((void**)&p_bo,  g_bo);

    const size_t sm1 = (128*(FIN+4) + (size_t)FIN*HH) * sizeof(float);
    const size_t sm2 = (128*(HH+4)  + (size_t)HH*HH)  * sizeof(float);
    const size_t sm3 = (128*(HH+4)  + (size_t)HH*FOUT)* sizeof(float);
    cudaFuncSetAttribute(gemm_kernel<FIN,HH,true,0,false>,    cudaFuncAttributeMaxDynamicSharedMemorySize, (int)sm1);
    cudaFuncSetAttribute(gemm_kernel<HH,HH,false,-1,true>,    cudaFuncAttributeMaxDynamicSharedMemorySize, (int)sm2);
    cudaFuncSetAttribute(gemm_kernel<HH,HH,true,2,false>,     cudaFuncAttributeMaxDynamicSharedMemorySize, (int)sm2);
    cudaFuncSetAttribute(gemm_kernel<HH,FOUT,false,-1,false>, cudaFuncAttributeMaxDynamicSharedMemorySize, (int)sm3);

    // init + CSR build
    init_kernel<<<TOT/256 + 1, 256>>>(b02, Wc, bc);
    count_kernel<<<(BB*EE)/256, 256>>>(erow);
    scan_kernel<<<BB, 1024>>>();
    scatter_kernel<<<(BB*EE)/256, 256>>>(erow, ecol, evl);

    // layer 0: h0 = relu(x@W0 + b0), bn0 stats fused
    gemm_kernel<FIN,HH,true,0,false><<<TOT/128, 256, sm1>>>(x, W0, b0, p_h0);

    // fold bn0 into (W02@Wc)
    mm128_kernel<<<HH, HH>>>(W02, Wc);
    fold_kernel<<<1, 128>>>(bn0w, bn0b, 0, p_M, p_Wa, p_ba, p_ba, HH);

    // hc = h0 @ Wa + ba   (fp16x2 output)
    gemm_kernel<HH,HH,false,-1,true><<<TOT/128, 256, sm2>>>(p_h0, p_Wa, p_ba, p_hcp);

    // SGC aggregate (+mask, relu, bnc stats)
    agg_kernel<<<TOT/8, 128>>>(nn);

    // fold bnc into W1
    fold_kernel<<<1, 128>>>(bncw, bncb, 1, W1, p_Wb, b1, p_bb, HH);

    // h2 = relu(h1 @ Wb + bb), bn1 stats fused
    gemm_kernel<HH,HH,true,2,false><<<TOT/128, 256, sm2>>>(p_h1, p_Wb, p_bb, p_h2);

    // fold bn1 into W2
    fold_kernel<<<1, 128>>>(bn1w, bn1b, 2, W2, p_Wo, b2, p_bo, FOUT);

    // out = h2 @ Wo + bo
    gemm_kernel<HH,FOUT,false,-1,false><<<TOT/128, 256, sm3>>>(p_h2, p_Wo, p_bo, out);
}